// round 13
// baseline (speedup 1.0000x reference)
#include <cuda_runtime.h>
#include <cuda_bf16.h>
#include <math.h>
#include <stddef.h>

// Problem dims (fixed)
#define SS 512
#define BB 64
#define II 32
#define HH 64
#define DD 128
#define FF 256
#define NHH 8
#define HDD 16
#define MR (SS*BB)   // 32768 rows
#define NCAT 512     // proj(128) + qkv(384) merged output width
#define QKVW 384

// ---------------- scratch (device globals) ----------------------------------
__device__ float g_xwf[SS*BB*HH];          // xW in RNN C-fragment layout
__device__ float g_hs[MR*HH];
__device__ float g_proj[MR*DD];            // fp32 proj (residual path)
__device__ __nv_bfloat16 g_qkvh[MR*QKVW];  // bf16 [q|k|v]
__device__ float g_ctx[MR*DD];
__device__ float g_x1[MR*DD];
__device__ float g_ffh[MR*FF];
__device__ float g_pool[BB*DD];            // atomic pool accumulator
__device__ float g_Wcat[NCAT*HH];          // [Wp ; Wqkv@Wp] (q rows pre-scaled)
__device__ float g_bcat[NCAT];

// ---------------- cp.async helpers ------------------------------------------
#define CP_ASYNC16(dst_u32, src) \
    asm volatile("cp.async.cg.shared.global [%0], [%1], 16;\n" :: "r"(dst_u32), "l"(src))
#define CP_COMMIT() asm volatile("cp.async.commit_group;\n")
#define CP_WAIT1()  asm volatile("cp.async.wait_group 1;\n")
#define CP_WAIT0()  asm volatile("cp.async.wait_group 0;\n")

#define LOG2E 1.4426950408889634f

__device__ __forceinline__ unsigned f2tf(float f) {
    unsigned r; asm("cvt.rna.tf32.f32 %0, %1;" : "=r"(r) : "f"(f)); return r;
}
__device__ __forceinline__ float fast_tanh(float x) {
    float r; asm("tanh.approx.f32 %0, %1;" : "=f"(r) : "f"(x)); return r;
}
__device__ __forceinline__ float ex2(float x) {
    float r; asm("ex2.approx.f32 %0, %1;" : "=f"(r) : "f"(x)); return r;
}
__device__ __forceinline__ unsigned pack_bf16(float lo, float hi) {
    unsigned r; asm("cvt.rn.bf16x2.f32 %0, %1, %2;" : "=r"(r) : "f"(hi), "f"(lo)); return r;
}
__device__ __forceinline__ unsigned pack_f16(float lo, float hi) {
    unsigned r; asm("cvt.rn.f16x2.f32 %0, %1, %2;" : "=r"(r) : "f"(hi), "f"(lo)); return r;
}
__device__ __forceinline__ void mma_tf32(float* c, const unsigned* a, const unsigned* b) {
    asm volatile(
        "mma.sync.aligned.m16n8k8.row.col.f32.tf32.tf32.f32 "
        "{%0,%1,%2,%3}, {%4,%5,%6,%7}, {%8,%9}, {%0,%1,%2,%3};"
        : "+f"(c[0]), "+f"(c[1]), "+f"(c[2]), "+f"(c[3])
        : "r"(a[0]), "r"(a[1]), "r"(a[2]), "r"(a[3]), "r"(b[0]), "r"(b[1]));
}
__device__ __forceinline__ void mma_bf16(float* c, const unsigned* a, const unsigned* b) {
    asm volatile(
        "mma.sync.aligned.m16n8k16.row.col.f32.bf16.bf16.f32 "
        "{%0,%1,%2,%3}, {%4,%5,%6,%7}, {%8,%9}, {%0,%1,%2,%3};"
        : "+f"(c[0]), "+f"(c[1]), "+f"(c[2]), "+f"(c[3])
        : "r"(a[0]), "r"(a[1]), "r"(a[2]), "r"(a[3]), "r"(b[0]), "r"(b[1]));
}
__device__ __forceinline__ void mma_f16(float* c, const unsigned* a, const unsigned* b) {
    asm volatile(
        "mma.sync.aligned.m16n8k16.row.col.f32.f16.f16.f32 "
        "{%0,%1,%2,%3}, {%4,%5,%6,%7}, {%8,%9}, {%0,%1,%2,%3};"
        : "+f"(c[0]), "+f"(c[1]), "+f"(c[2]), "+f"(c[3])
        : "r"(a[0]), "r"(a[1]), "r"(a[2]), "r"(a[3]), "r"(b[0]), "r"(b[1]));
}

// ---------------- zero pool accumulator --------------------------------------
__global__ __launch_bounds__(128) void zero_pool_kernel()
{
    g_pool[blockIdx.x * 128 + threadIdx.x] = 0.f;
}

// ---------------- kernel 1: xW = x @ W_ih^T + b_ih + b_hh (fragment layout) --
// Writes xw value for (s, b, j) into the RNN MMA C-fragment position:
//   Bk = b>>5 (rnn block), w = (b>>3)&3 (warp), g = b&7 (row),
//   nt = j>>3, t4 = (j&7)>>1, odd = j&1, lane = g*4+t4
//   idx = ((s*8 + Bk*4 + w)*32 + lane)*16 + nt*2 + odd
__global__ __launch_bounds__(64) void xw_kernel(
    const float* __restrict__ x, const float* __restrict__ W_ih,
    const float* __restrict__ b_ih, const float* __restrict__ b_hh)
{
    int sb = blockIdx.x;
    int s = sb >> 6, b = sb & 63;
    int j = threadIdx.x;
    __shared__ float xs[II];
    if (j < II) xs[j] = x[((size_t)b*SS + s)*II + j];
    __syncthreads();
    float acc = b_ih[j] + b_hh[j];
    const float* w = W_ih + (size_t)j*II;
    #pragma unroll
    for (int i = 0; i < II; i += 4) {
        float4 wv = *(const float4*)(w + i);
        float4 xv = *(const float4*)(xs + i);
        acc += wv.x*xv.x + wv.y*xv.y + wv.z*xv.z + wv.w*xv.w;
    }
    int Bk = b >> 5, wq = (b >> 3) & 3, g = b & 7;
    int nt = j >> 3, t4 = (j & 7) >> 1, odd = j & 1;
    int lane = g*4 + t4;
    size_t idx = ((size_t)(s*8 + Bk*4 + wq)*32 + lane)*16 + nt*2 + odd;
    g_xwf[idx] = acc;
}

// ---------------- weight build: Wcat = [Wp ; Wqkv@Wp], q rows pre-scaled ----
__global__ __launch_bounds__(64) void fold_kernel(
    const float* __restrict__ Wqkv, const float* __restrict__ bqkv,
    const float* __restrict__ Wp, const float* __restrict__ bp)
{
    int n = blockIdx.x;
    int k = threadIdx.x;
    if (n < DD) {
        g_Wcat[(size_t)n*HH + k] = Wp[(size_t)n*HH + k];
        if (k == 0) g_bcat[n] = bp[n];
        return;
    }
    int nq = n - DD;
    float scale = (n < 2*DD) ? 0.25f * LOG2E : 1.f;
    __shared__ float wrow[DD];
    __shared__ float ws[2];
    wrow[k]      = Wqkv[(size_t)nq*DD + k];
    wrow[k + 64] = Wqkv[(size_t)nq*DD + 64 + k];
    __syncthreads();
    float acc = 0.f;
    #pragma unroll 8
    for (int d = 0; d < DD; d++) acc += wrow[d] * Wp[(size_t)d*HH + k];
    g_Wcat[(size_t)n*HH + k] = acc * scale;
    float pd = wrow[k]*bp[k] + wrow[k+64]*bp[k+64];
    #pragma unroll
    for (int o = 16; o > 0; o >>= 1) pd += __shfl_xor_sync(0xffffffffu, pd, o);
    if ((k & 31) == 0) ws[k >> 5] = pd;
    __syncthreads();
    if (k == 0) g_bcat[n] = (bqkv[nq] + ws[0] + ws[1]) * scale;
}

// ---------------- kernel 2: tensor-core RNN recurrence ----------------------
// 2 blocks x 4 warps; warp owns 8 batches (m16 rows 0-7; rows 8-15 are zero).
// h state lives in f16 A-fragments; C->A via the n-tile-pair bf16x2 pack trick
// (no shuffles, no smem, no barriers). xw pre-swizzled to C-frag layout.
__global__ __launch_bounds__(128) void rnn_mma(const float* __restrict__ W_hh)
{
    const int Bk = blockIdx.x;             // 0..1
    const int w = threadIdx.x >> 5;
    const int lane = threadIdx.x & 31;
    const int g = lane >> 2, t4 = lane & 3;
    const int bb = Bk*32 + w*8 + g;        // batch this (lane-row g) handles

    // W_hh B-fragments in f16: wb[nt][ku][2]
    unsigned wb[8][4][2];
    #pragma unroll
    for (int nt = 0; nt < 8; nt++) {
        const float* wr = W_hh + (size_t)(nt*8 + g)*HH;
        #pragma unroll
        for (int ku = 0; ku < 4; ku++) {
            int k0 = ku*16 + 2*t4;
            wb[nt][ku][0] = pack_f16(wr[k0],     wr[k0 + 1]);
            wb[nt][ku][1] = pack_f16(wr[k0 + 8], wr[k0 + 9]);
        }
    }

    // h A-fragments (f16), init h=0
    unsigned ha[4][4];
    #pragma unroll
    for (int u = 0; u < 4; u++) {
        ha[u][0] = 0u; ha[u][1] = 0u; ha[u][2] = 0u; ha[u][3] = 0u;
    }

    // xw prefetch (16 floats = this lane's c0/c1 across 8 n-tiles)
    const float4* xp = (const float4*)&g_xwf[((size_t)(0*8 + Bk*4 + w)*32 + lane)*16];
    float4 xr0 = xp[0], xr1 = xp[1], xr2 = xp[2], xr3 = xp[3];

    float* hsbase = &g_hs[(size_t)bb*HH + 2*t4];

    for (int s = 0; s < SS; s++) {
        // C init: c0,c1 = xw; c2,c3 (garbage rows) = 0
        float c[8][4];
        c[0][0]=xr0.x; c[0][1]=xr0.y; c[1][0]=xr0.z; c[1][1]=xr0.w;
        c[2][0]=xr1.x; c[2][1]=xr1.y; c[3][0]=xr1.z; c[3][1]=xr1.w;
        c[4][0]=xr2.x; c[4][1]=xr2.y; c[5][0]=xr2.z; c[5][1]=xr2.w;
        c[6][0]=xr3.x; c[6][1]=xr3.y; c[7][0]=xr3.z; c[7][1]=xr3.w;
        #pragma unroll
        for (int nt = 0; nt < 8; nt++) { c[nt][2] = 0.f; c[nt][3] = 0.f; }

        // prefetch next step's xw
        if (s + 1 < SS) {
            const float4* xn = (const float4*)&g_xwf[((size_t)((s+1)*8 + Bk*4 + w)*32 + lane)*16];
            xr0 = xn[0]; xr1 = xn[1]; xr2 = xn[2]; xr3 = xn[3];
        }

        // C += H @ W_hh^T  (32 f16 MMAs)
        #pragma unroll
        for (int ku = 0; ku < 4; ku++)
            #pragma unroll
            for (int nt = 0; nt < 8; nt++)
                mma_f16(c[nt], ha[ku], wb[nt][ku]);

        // tanh (valid rows only), rebuild A-frags, store h (f32)
        float* hs = hsbase + (size_t)(s*BB)*HH;
        #pragma unroll
        for (int u = 0; u < 4; u++) {
            float t00 = fast_tanh(c[2*u][0]);
            float t01 = fast_tanh(c[2*u][1]);
            float t10 = fast_tanh(c[2*u+1][0]);
            float t11 = fast_tanh(c[2*u+1][1]);
            ha[u][0] = pack_f16(t00, t01);
            ha[u][2] = pack_f16(t10, t11);
            // ha[u][1], ha[u][3] stay 0 (garbage rows)
            *(float2*)(hs + (2*u)*8)   = make_float2(t00, t01);
            *(float2*)(hs + (2*u+1)*8) = make_float2(t10, t11);
        }
    }
}

// ---------------- tf32 tensor-core GEMM (cp.async): C = A @ W^T + bias ------
// MODE 0: +bias  MODE 1: +bias,relu
// MODE 2: C = LN(R1 + acc+bias)
// MODE 3: atomic-accumulate LN(LN(R1+acc+bias)+R2) into g_pool (no C write)
// MODE 4: split output: block col 0 -> g_proj fp32; cols 1..3 -> g_qkvh bf16
#define LDT 36
#define A_STAGE (128*LDT)
#define B_STAGE (128*LDT)
#define CS_LD 132

template<int MODE>
__global__ __launch_bounds__(256, 2) void mma_gemm(
    const float* __restrict__ A, const float* __restrict__ W,
    const float* __restrict__ bias,
    const float* __restrict__ R1, const float* __restrict__ R2,
    const float* __restrict__ gA, const float* __restrict__ bA,
    const float* __restrict__ gB, const float* __restrict__ bB,
    float* __restrict__ C, int M, int N, int K, int rs1, int rs2)
{
    extern __shared__ float sh[];
    float* As = sh;
    float* Bs = sh + 2*A_STAGE;
    float* Cs = sh;

    const int tid = threadIdx.x;
    const int lane = tid & 31, wid = tid >> 5;
    const int wm = wid >> 2, wn = wid & 3;
    const int g = lane >> 2, t4 = lane & 3;
    const int bm = blockIdx.y * 128;
    const int bn = blockIdx.x * 128;
    const int lrow = tid >> 3;
    const int lcol = (tid & 7) << 2;

    float acc[4][4][4];
    #pragma unroll
    for (int mt = 0; mt < 4; mt++)
        #pragma unroll
        for (int nt = 0; nt < 4; nt++)
            #pragma unroll
            for (int i = 0; i < 4; i++) acc[mt][nt][i] = 0.f;

    const int nk = K >> 5;

    #define ISSUE_TILE(kt0, buf) do {                                           \
        float* Ab = As + (buf)*A_STAGE;                                         \
        float* Bb = Bs + (buf)*B_STAGE;                                         \
        _Pragma("unroll")                                                       \
        for (int i = 0; i < 4; i++) {                                           \
            int row = lrow + 32*i;                                              \
            unsigned d = (unsigned)__cvta_generic_to_shared(Ab + row*LDT + lcol); \
            CP_ASYNC16(d, &A[(size_t)(bm + row)*K + (kt0) + lcol]);             \
        }                                                                       \
        _Pragma("unroll")                                                       \
        for (int i = 0; i < 4; i++) {                                           \
            int row = lrow + 32*i;                                              \
            unsigned d = (unsigned)__cvta_generic_to_shared(Bb + row*LDT + lcol); \
            CP_ASYNC16(d, &W[(size_t)(bn + row)*K + (kt0) + lcol]);             \
        }                                                                       \
        CP_COMMIT();                                                            \
    } while (0)

    ISSUE_TILE(0, 0);

    for (int kt = 0; kt < nk; kt++) {
        int cur = kt & 1;
        if (kt + 1 < nk) { ISSUE_TILE((kt + 1) << 5, cur ^ 1); CP_WAIT1(); }
        else             { CP_WAIT0(); }
        __syncthreads();
        const float* Ab = As + cur*A_STAGE;
        const float* Bb = Bs + cur*B_STAGE;
        #pragma unroll
        for (int ks = 0; ks < 4; ks++) {
            int kb = ks*8;
            unsigned af[4][4];
            #pragma unroll
            for (int mt = 0; mt < 4; mt++) {
                int r0 = wm*64 + mt*16 + g;
                af[mt][0] = f2tf(Ab[r0*LDT + kb + t4]);
                af[mt][1] = f2tf(Ab[(r0+8)*LDT + kb + t4]);
                af[mt][2] = f2tf(Ab[r0*LDT + kb + t4 + 4]);
                af[mt][3] = f2tf(Ab[(r0+8)*LDT + kb + t4 + 4]);
            }
            #pragma unroll
            for (int nt = 0; nt < 4; nt++) {
                int nrow = wn*32 + nt*8 + g;
                unsigned bf[2];
                bf[0] = f2tf(Bb[nrow*LDT + kb + t4]);
                bf[1] = f2tf(Bb[nrow*LDT + kb + t4 + 4]);
                #pragma unroll
                for (int mt = 0; mt < 4; mt++) mma_tf32(acc[mt][nt], af[mt], bf);
            }
        }
        __syncthreads();
    }

    if (MODE <= 1) {
        #pragma unroll
        for (int mt = 0; mt < 4; mt++) {
            int row0 = bm + wm*64 + mt*16 + g;
            #pragma unroll
            for (int nt = 0; nt < 4; nt++) {
                int col = bn + wn*32 + nt*8 + t4*2;
                float2 bz = *(const float2*)&bias[col];
                float2 o0 = {acc[mt][nt][0] + bz.x, acc[mt][nt][1] + bz.y};
                float2 o1 = {acc[mt][nt][2] + bz.x, acc[mt][nt][3] + bz.y};
                if (MODE == 1) {
                    o0.x = fmaxf(o0.x, 0.f); o0.y = fmaxf(o0.y, 0.f);
                    o1.x = fmaxf(o1.x, 0.f); o1.y = fmaxf(o1.y, 0.f);
                }
                *(float2*)&C[(size_t)row0*N + col] = o0;
                *(float2*)&C[(size_t)(row0+8)*N + col] = o1;
            }
        }
    } else if (MODE == 4) {
        #pragma unroll
        for (int mt = 0; mt < 4; mt++) {
            int row0 = bm + wm*64 + mt*16 + g;
            #pragma unroll
            for (int nt = 0; nt < 4; nt++) {
                int coln = bn + wn*32 + nt*8 + t4*2;
                float2 bz = *(const float2*)&bias[coln];
                float2 o0 = {acc[mt][nt][0] + bz.x, acc[mt][nt][1] + bz.y};
                float2 o1 = {acc[mt][nt][2] + bz.x, acc[mt][nt][3] + bz.y};
                if (blockIdx.x == 0) {
                    int col = coln;
                    *(float2*)&g_proj[(size_t)row0*DD + col] = o0;
                    *(float2*)&g_proj[(size_t)(row0+8)*DD + col] = o1;
                } else {
                    int col = coln - DD;
                    *(unsigned*)&g_qkvh[(size_t)row0*QKVW + col] = pack_bf16(o0.x, o0.y);
                    *(unsigned*)&g_qkvh[(size_t)(row0+8)*QKVW + col] = pack_bf16(o1.x, o1.y);
                }
            }
        }
    } else {
        #pragma unroll
        for (int mt = 0; mt < 4; mt++) {
            int r0 = wm*64 + mt*16 + g;
            #pragma unroll
            for (int nt = 0; nt < 4; nt++) {
                int col = wn*32 + nt*8 + t4*2;
                *(float2*)&Cs[r0*CS_LD + col]     = make_float2(acc[mt][nt][0], acc[mt][nt][1]);
                *(float2*)&Cs[(r0+8)*CS_LD + col] = make_float2(acc[mt][nt][2], acc[mt][nt][3]);
            }
        }
        __syncthreads();
        float4 bz = *(const float4*)&bias[lane*4];
        float4 ga4 = *(const float4*)&gA[lane*4];
        float4 ba4 = *(const float4*)&bA[lane*4];
        #pragma unroll
        for (int i = 0; i < 16; i++) {
            int r = wid*16 + i;
            size_t gr = (size_t)(bm + r);
            float4 v = *(const float4*)&Cs[r*CS_LD + lane*4];
            float4 r1 = *(const float4*)&R1[gr*rs1 + lane*4];
            float v0 = v.x + bz.x + r1.x, v1 = v.y + bz.y + r1.y;
            float v2 = v.z + bz.z + r1.z, v3 = v.w + bz.w + r1.w;
            float s = v0 + v1 + v2 + v3;
            #pragma unroll
            for (int o = 16; o > 0; o >>= 1) s += __shfl_xor_sync(0xffffffffu, s, o);
            float mu = s * (1.f/128.f);
            float d0 = v0-mu, d1 = v1-mu, d2 = v2-mu, d3 = v3-mu;
            float qv = d0*d0 + d1*d1 + d2*d2 + d3*d3;
            #pragma unroll
            for (int o = 16; o > 0; o >>= 1) qv += __shfl_xor_sync(0xffffffffu, qv, o);
            float inv = rsqrtf(qv * (1.f/128.f) + 1e-5f);
            float x0 = d0*inv*ga4.x + ba4.x;
            float x1 = d1*inv*ga4.y + ba4.y;
            float x2 = d2*inv*ga4.z + ba4.z;
            float x3 = d3*inv*ga4.w + ba4.w;
            if (MODE == 2) {
                *(float4*)&C[gr*DD + lane*4] = make_float4(x0, x1, x2, x3);
            } else {
                float4 r2 = *(const float4*)&R2[gr*rs2 + lane*4];
                float4 gb4 = *(const float4*)&gB[lane*4];
                float4 bb4 = *(const float4*)&bB[lane*4];
                float u0 = x0 + r2.x, u1 = x1 + r2.y, u2 = x2 + r2.z, u3 = x3 + r2.w;
                float s2 = u0 + u1 + u2 + u3;
                #pragma unroll
                for (int o = 16; o > 0; o >>= 1) s2 += __shfl_xor_sync(0xffffffffu, s2, o);
                float mu2 = s2 * (1.f/128.f);
                float e0 = u0-mu2, e1 = u1-mu2, e2 = u2-mu2, e3 = u3-mu2;
                float q2 = e0*e0 + e1*e1 + e2*e2 + e3*e3;
                #pragma unroll
                for (int o = 16; o > 0; o >>= 1) q2 += __shfl_xor_sync(0xffffffffu, q2, o);
                float inv2 = rsqrtf(q2 * (1.f/128.f) + 1e-5f);
                int bb = (int)(gr & 63);
                float* pp = &g_pool[bb*DD + lane*4];
                atomicAdd(pp + 0, e0*inv2*gb4.x + bb4.x);
                atomicAdd(pp + 1, e1*inv2*gb4.y + bb4.y);
                atomicAdd(pp + 2, e2*inv2*gb4.z + bb4.z);
                atomicAdd(pp + 3, e3*inv2*gb4.w + bb4.w);
            }
        }
    }
    #undef ISSUE_TILE
}

// ---------------- flash attention: all-bf16 MMA, no-max softmax -------------
#define TK 32
#define KVH 24
#define NT_TILES (SS/TK)
__global__ __launch_bounds__(256) void attn_mma(
    const __nv_bfloat16* __restrict__ qkvh, float* __restrict__ ctx)
{
    __shared__ __align__(16) __nv_bfloat16 Kt[2][TK][KVH];
    __shared__ __align__(16) __nv_bfloat16 Vt[2][TK][KVH];
    const int bh = blockIdx.x;
    const int b = bh >> 3, h = bh & 7;
    const int tid = threadIdx.x, lane = tid & 31, w = tid >> 5;
    const int g = lane >> 2, t4 = lane & 3;

    #define ISSUE_KV(tk_, buf) do {                                               \
        if (tid < 128) {                                                          \
            int row = (tid & 63) >> 1, ch = tid & 1;                              \
            int off = (tid < 64) ? DD : 2*DD;                                     \
            const __nv_bfloat16* src = qkvh +                                     \
                (size_t)(((tk_)*TK + row)*BB + b)*QKVW + off + h*HDD + ch*8;      \
            __nv_bfloat16* dst = (tid < 64) ? &Kt[buf][row][ch*8]                 \
                                            : &Vt[buf][row][ch*8];                \
            unsigned d = (unsigned)__cvta_generic_to_shared(dst);                 \
            CP_ASYNC16(d, src);                                                   \
        }                                                                         \
        CP_COMMIT();                                                              \
    } while (0)

    unsigned qa[4][4];
    #pragma unroll
    for (int mt = 0; mt < 4; mt++) {
        int r0 = w*64 + mt*16 + g;
        const __nv_bfloat16* p0 = qkvh + (size_t)(r0*BB + b)*QKVW + h*HDD;
        const __nv_bfloat16* p1 = p0 + (size_t)8*BB*QKVW;
        qa[mt][0] = *(const unsigned*)(p0 + 2*t4);
        qa[mt][1] = *(const unsigned*)(p1 + 2*t4);
        qa[mt][2] = *(const unsigned*)(p0 + 2*t4 + 8);
        qa[mt][3] = *(const unsigned*)(p1 + 2*t4 + 8);
    }

    float lsum[8], o[4][2][4];
    #pragma unroll
    for (int i = 0; i < 8; i++) lsum[i] = 0.f;
    #pragma unroll
    for (int mt = 0; mt < 4; mt++)
        #pragma unroll
        for (int n8 = 0; n8 < 2; n8++)
            #pragma unroll
            for (int i = 0; i < 4; i++) o[mt][n8][i] = 0.f;

    ISSUE_KV(0, 0);

    for (int tk = 0; tk < NT_TILES; tk++) {
        int cur = tk & 1;
        if (tk + 1 < NT_TILES) { ISSUE_KV(tk + 1, cur ^ 1); CP_WAIT1(); }
        else                   { CP_WAIT0(); }
        __syncthreads();

        float sc[4][4][4];
        #pragma unroll
        for (int mt = 0; mt < 4; mt++)
            #pragma unroll
            for (int nt = 0; nt < 4; nt++)
                #pragma unroll
                for (int i = 0; i < 4; i++) sc[mt][nt][i] = 0.f;
        #pragma unroll
        for (int nt = 0; nt < 4; nt++) {
            unsigned bf[2];
            bf[0] = *(const unsigned*)&Kt[cur][nt*8+g][2*t4];
            bf[1] = *(const unsigned*)&Kt[cur][nt*8+g][2*t4 + 8];
            #pragma unroll
            for (int mt = 0; mt < 4; mt++) mma_bf16(sc[mt][nt], qa[mt], bf);
        }

        #pragma unroll
        for (int mt = 0; mt < 4; mt++) {
            #pragma unroll
            for (int nt = 0; nt < 4; nt++) {
                float e0 = ex2(sc[mt][nt][0]);
                float e1 = ex2(sc[mt][nt][1]);
                float e2 = ex2(sc[mt][nt][2]);
                float e3 = ex2(sc[mt][nt][3]);
                sc[mt][nt][0] = e0; sc[mt][nt][1] = e1;
                sc[mt][nt][2] = e2; sc[mt][nt][3] = e3;
                lsum[mt*2+0] += e0 + e1;
                lsum[mt*2+1] += e2 + e3;
            }
        }

        #pragma unroll
        for (int u = 0; u < 2; u++) {
            unsigned vb[2][2];
            #pragma unroll
            for (int n8 = 0; n8 < 2; n8++) {
                int d = n8*8 + g;
                unsigned lo0 = *(const unsigned short*)&Vt[cur][u*16 + 2*t4][d];
                unsigned hi0 = *(const unsigned short*)&Vt[cur][u*16 + 2*t4 + 1][d];
                unsigned lo1 = *(const unsigned short*)&Vt[cur][u*16 + 2*t4 + 8][d];
                unsigned hi1 = *(const unsigned short*)&Vt[cur][u*16 + 2*t4 + 9][d];
                vb[n8][0] = lo0 | (hi0 << 16);
                vb[n8][1] = lo1 | (hi1 << 16);
            }
            #pragma unroll
            for (int mt = 0; mt < 4; mt++) {
                unsigned pa[4];
                pa[0] = pack_bf16(sc[mt][u*2][0],   sc[mt][u*2][1]);
                pa[1] = pack_bf16(sc[mt][u*2][2],   sc[mt][u*2][3]);
                pa[2] = pack_bf16(sc[mt][u*2+1][0], sc[mt][u*2+1][1]);
                pa[3] = pack_bf16(sc[mt][u*2+1][2], sc[mt][u*2+1][3]);
                mma_bf16(o[mt][0], pa, vb[0]);
                mma_bf16(o[mt][1], pa, vb[1]);
            }
        }
        __syncthreads();
    }

    float inv[8];
    #pragma unroll
    for (int i = 0; i < 8; i++) {
        float l = lsum[i];
        l += __shfl_xor_sync(0xffffffffu, l, 1);
        l += __shfl_xor_sync(0xffffffffu, l, 2);
        inv[i] = 1.f / l;
    }
    #pragma unroll
    for (int mt = 0; mt < 4; mt++) {
        int r0 = w*64 + mt*16 + g;
        #pragma unroll
        for (int n8 = 0; n8 < 2; n8++) {
            int col = h*HDD + n8*8 + 2*t4;
            float2 lo = { o[mt][n8][0]*inv[mt*2],   o[mt][n8][1]*inv[mt*2]   };
            float2 hi = { o[mt][n8][2]*inv[mt*2+1], o[mt][n8][3]*inv[mt*2+1] };
            *(float2*)&ctx[(size_t)(r0*BB + b)*DD + col]     = lo;
            *(float2*)&ctx[(size_t)((r0+8)*BB + b)*DD + col] = hi;
        }
    }
    #undef ISSUE_KV
}

// ---------------- head: tanh(pool/S @ Wf^T + bf) ----------------------------
__global__ __launch_bounds__(128) void final_kernel(
    const float* __restrict__ Wf, const float* __restrict__ bf,
    float* __restrict__ out)
{
    int b = blockIdx.x, tid = threadIdx.x;
    __shared__ float p[DD];
    p[tid] = g_pool[b*DD + tid] * (1.f/(float)SS);
    __syncthreads();
    int i = tid >> 2, q = tid & 3;
    const float* w = Wf + (size_t)i*DD + q*32;
    const float* pv = p + q*32;
    float acc = 0.f;
    #pragma unroll
    for (int k = 0; k < 32; k += 4) {
        float4 wv = *(const float4*)(w + k);
        float4 xv = *(const float4*)(pv + k);
        acc += wv.x*xv.x + wv.y*xv.y + wv.z*xv.z + wv.w*xv.w;
    }
    acc += __shfl_xor_sync(0xffffffffu, acc, 1);
    acc += __shfl_xor_sync(0xffffffffu, acc, 2);
    if (q == 0) out[b*II + i] = tanhf(acc + bf[i]);
}

// ---------------- launch ----------------------------------------------------
static const int GEMM_SMEM = (2*A_STAGE + 2*B_STAGE) * (int)sizeof(float); // 73728

extern "C" void kernel_launch(void* const* d_in, const int* in_sizes, int n_in,
                              void* d_out, int out_size)
{
    const float* x    = (const float*)d_in[0];
    const float* W_ih = (const float*)d_in[1];
    const float* b_ih = (const float*)d_in[2];
    const float* W_hh = (const float*)d_in[3];
    const float* b_hh = (const float*)d_in[4];
    const float* Wp   = (const float*)d_in[5];
    const float* bp   = (const float*)d_in[6];
    const float* Wqkv = (const float*)d_in[7];
    const float* bqkv = (const float*)d_in[8];
    const float* Wo   = (const float*)d_in[9];
    const float* bo   = (const float*)d_in[10];
    const float* g1   = (const float*)d_in[11];
    const float* be1  = (const float*)d_in[12];
    const float* W1   = (const float*)d_in[13];
    const float* b1   = (const float*)d_in[14];
    const float* W2   = (const float*)d_in[15];
    const float* b2   = (const float*)d_in[16];
    const float* g2   = (const float*)d_in[17];
    const float* be2  = (const float*)d_in[18];
    const float* gn   = (const float*)d_in[19];
    const float* bn   = (const float*)d_in[20];
    const float* Wf   = (const float*)d_in[21];
    const float* bf   = (const float*)d_in[22];
    float* out = (float*)d_out;

    float *p_hs, *p_proj, *p_ctx, *p_x1, *p_ffh, *p_Wcat, *p_bcat;
    __nv_bfloat16* p_qkvh;
    cudaGetSymbolAddress((void**)&p_hs,    g_hs);
    cudaGetSymbolAddress((void**)&p_proj,  g_proj);
    cudaGetSymbolAddress((void**)&p_qkvh,  g_qkvh);
    cudaGetSymbolAddress((void**)&p_ctx,   g_ctx);
    cudaGetSymbolAddress((void**)&p_x1,    g_x1);
    cudaGetSymbolAddress((void**)&p_ffh,   g_ffh);
    cudaGetSymbolAddress((void**)&p_Wcat,  g_Wcat);
    cudaGetSymbolAddress((void**)&p_bcat,  g_bcat);

    cudaFuncSetAttribute(mma_gemm<1>, cudaFuncAttributeMaxDynamicSharedMemorySize, GEMM_SMEM);
    cudaFuncSetAttribute(mma_gemm<2>, cudaFuncAttributeMaxDynamicSharedMemorySize, GEMM_SMEM);
    cudaFuncSetAttribute(mma_gemm<3>, cudaFuncAttributeMaxDynamicSharedMemorySize, GEMM_SMEM);
    cudaFuncSetAttribute(mma_gemm<4>, cudaFuncAttributeMaxDynamicSharedMemorySize, GEMM_SMEM);

    // 0. build weights + zero pool accumulator
    fold_kernel<<<NCAT, 64>>>(Wqkv, bqkv, Wp, bp);
    zero_pool_kernel<<<BB, 128>>>();
    // 1. parallel part of the RNN cell (fragment-layout output)
    xw_kernel<<<SS*BB, 64>>>(x, W_ih, b_ih, b_hh);
    // 2. tensor-core RNN recurrence (2 blocks, no barriers)
    rnn_mma<<<2, 128>>>(W_hh);
    // 3. split-output GEMM: proj fp32 + qkv bf16 (q pre-scaled)
    mma_gemm<4><<<dim3(NCAT/128, MR/128), 256, GEMM_SMEM>>>(
        p_hs, p_Wcat, p_bcat, nullptr, nullptr, nullptr, nullptr, nullptr, nullptr,
        nullptr, MR, NCAT, HH, 0, 0);
    // 4. attention (all-bf16 MMA, no-max softmax)
    attn_mma<<<BB*NHH, 256>>>(p_qkvh, p_ctx);
    // 5. x1 = LN(proj + ctx@Wo^T + bo)
    mma_gemm<2><<<dim3(1, MR/128), 256, GEMM_SMEM>>>(
        p_ctx, Wo, bo, p_proj, nullptr, g1, be1, nullptr, nullptr,
        p_x1, MR, DD, DD, DD, 0);
    // 6. ffh = relu(x1 @ W1^T + b1)
    mma_gemm<1><<<dim3(2, MR/128), 256, GEMM_SMEM>>>(
        p_x1, W1, b1, nullptr, nullptr, nullptr, nullptr, nullptr, nullptr,
        p_ffh, MR, FF, DD, 0, 0);
    // 7. LN(LN(x1 + ffh@W2^T + b2) + proj) -> atomic pool accumulate
    mma_gemm<3><<<dim3(1, MR/128), 256, GEMM_SMEM>>>(
        p_ffh, W2, b2, p_x1, p_proj, g2, be2, gn, bn,
        nullptr, MR, DD, FF, DD, DD);
    // 8. pooled head
    final_kernel<<<BB, 128>>>(Wf, bf, out);
}

// round 15
// speedup vs baseline: 1.3871x; 1.3871x over previous
#include <cuda_runtime.h>
#include <cuda_bf16.h>
#include <math.h>
#include <stddef.h>

// Problem dims (fixed)
#define SS 512
#define BB 64
#define II 32
#define HH 64
#define DD 128
#define FF 256
#define NHH 8
#define HDD 16
#define MR (SS*BB)   // 32768 rows
#define NCAT 512     // proj(128) + qkv(384) merged output width
#define QKVW 384

// ---------------- scratch (device globals) ----------------------------------
__device__ float g_xw[SS*BB*HH];
__device__ float g_hs[MR*HH];
__device__ float g_proj[MR*DD];            // fp32 proj (residual path)
__device__ __nv_bfloat16 g_qkvh[MR*QKVW];  // bf16 [q|k|v]
__device__ float g_ctx[MR*DD];
__device__ float g_x1[MR*DD];
__device__ float g_ffh[MR*FF];
__device__ float g_pool[BB*DD];            // atomic pool accumulator
__device__ float g_Wcat[NCAT*HH];          // [Wp ; Wqkv@Wp] (q rows pre-scaled)
__device__ float g_bcat[NCAT];

// ---------------- cp.async helpers ------------------------------------------
#define CP_ASYNC16(dst_u32, src) \
    asm volatile("cp.async.cg.shared.global [%0], [%1], 16;\n" :: "r"(dst_u32), "l"(src))
#define CP_COMMIT() asm volatile("cp.async.commit_group;\n")
#define CP_WAIT1()  asm volatile("cp.async.wait_group 1;\n")
#define CP_WAIT0()  asm volatile("cp.async.wait_group 0;\n")

#define LOG2E 1.4426950408889634f

__device__ __forceinline__ unsigned f2tf(float f) {
    unsigned r; asm("cvt.rna.tf32.f32 %0, %1;" : "=r"(r) : "f"(f)); return r;
}
__device__ __forceinline__ float fast_tanh(float x) {
    float r; asm("tanh.approx.f32 %0, %1;" : "=f"(r) : "f"(x)); return r;
}
__device__ __forceinline__ float ex2(float x) {
    float r; asm("ex2.approx.f32 %0, %1;" : "=f"(r) : "f"(x)); return r;
}
__device__ __forceinline__ unsigned pack_bf16(float lo, float hi) {
    unsigned r; asm("cvt.rn.bf16x2.f32 %0, %1, %2;" : "=r"(r) : "f"(hi), "f"(lo)); return r;
}
__device__ __forceinline__ void mma_tf32(float* c, const unsigned* a, const unsigned* b) {
    asm volatile(
        "mma.sync.aligned.m16n8k8.row.col.f32.tf32.tf32.f32 "
        "{%0,%1,%2,%3}, {%4,%5,%6,%7}, {%8,%9}, {%0,%1,%2,%3};"
        : "+f"(c[0]), "+f"(c[1]), "+f"(c[2]), "+f"(c[3])
        : "r"(a[0]), "r"(a[1]), "r"(a[2]), "r"(a[3]), "r"(b[0]), "r"(b[1]));
}
__device__ __forceinline__ void mma_bf16(float* c, const unsigned* a, const unsigned* b) {
    asm volatile(
        "mma.sync.aligned.m16n8k16.row.col.f32.bf16.bf16.f32 "
        "{%0,%1,%2,%3}, {%4,%5,%6,%7}, {%8,%9}, {%0,%1,%2,%3};"
        : "+f"(c[0]), "+f"(c[1]), "+f"(c[2]), "+f"(c[3])
        : "r"(a[0]), "r"(a[1]), "r"(a[2]), "r"(a[3]), "r"(b[0]), "r"(b[1]));
}

// ---------------- zero pool accumulator --------------------------------------
__global__ __launch_bounds__(128) void zero_pool_kernel()
{
    g_pool[blockIdx.x * 128 + threadIdx.x] = 0.f;
}

// ---------------- kernel 1: xW = x @ W_ih^T + b_ih + b_hh -------------------
__global__ __launch_bounds__(64) void xw_kernel(
    const float* __restrict__ x, const float* __restrict__ W_ih,
    const float* __restrict__ b_ih, const float* __restrict__ b_hh)
{
    int sb = blockIdx.x;
    int s = sb >> 6, b = sb & 63;
    int j = threadIdx.x;
    __shared__ float xs[II];
    if (j < II) xs[j] = x[((size_t)b*SS + s)*II + j];
    __syncthreads();
    float acc = b_ih[j] + b_hh[j];
    const float* w = W_ih + (size_t)j*II;
    #pragma unroll
    for (int i = 0; i < II; i += 4) {
        float4 wv = *(const float4*)(w + i);
        float4 xv = *(const float4*)(xs + i);
        acc += wv.x*xv.x + wv.y*xv.y + wv.z*xv.z + wv.w*xv.w;
    }
    g_xw[(size_t)sb*HH + j] = acc;
}

// ---------------- weight build: Wcat = [Wp ; Wqkv@Wp], q rows pre-scaled ----
__global__ __launch_bounds__(64) void fold_kernel(
    const float* __restrict__ Wqkv, const float* __restrict__ bqkv,
    const float* __restrict__ Wp, const float* __restrict__ bp)
{
    int n = blockIdx.x;
    int k = threadIdx.x;
    if (n < DD) {
        g_Wcat[(size_t)n*HH + k] = Wp[(size_t)n*HH + k];
        if (k == 0) g_bcat[n] = bp[n];
        return;
    }
    int nq = n - DD;
    float scale = (n < 2*DD) ? 0.25f * LOG2E : 1.f;
    __shared__ float wrow[DD];
    __shared__ float ws[2];
    wrow[k]      = Wqkv[(size_t)nq*DD + k];
    wrow[k + 64] = Wqkv[(size_t)nq*DD + 64 + k];
    __syncthreads();
    float acc = 0.f;
    #pragma unroll 8
    for (int d = 0; d < DD; d++) acc += wrow[d] * Wp[(size_t)d*HH + k];
    g_Wcat[(size_t)n*HH + k] = acc * scale;
    float pd = wrow[k]*bp[k] + wrow[k+64]*bp[k+64];
    #pragma unroll
    for (int o = 16; o > 0; o >>= 1) pd += __shfl_xor_sync(0xffffffffu, pd, o);
    if ((k & 31) == 0) ws[k >> 5] = pd;
    __syncthreads();
    if (k == 0) g_bcat[n] = (bqkv[nq] + ws[0] + ws[1]) * scale;
}

// ---------------- kernel 2: sequential RNN recurrence, 4-deep prefetch ------
// 64 blocks (1 batch each), 128 threads (2 per hidden unit). xw loads are
// issued 4 steps ahead (MLP=4) so L2/DRAM latency is fully overlapped with
// the ~200-cycle arithmetic critical path.
__global__ __launch_bounds__(128) void rnn_kernel(const float* __restrict__ W_hh)
{
    int b = blockIdx.x;
    int tid = threadIdx.x;
    int j = tid >> 1;
    int half = tid & 1;
    float w[32];
    const float* wp = W_hh + (size_t)j*HH + half*32;
    #pragma unroll
    for (int k = 0; k < 32; k++) w[k] = wp[k];

    __shared__ float hbuf[2][HH];
    if (half == 0) hbuf[0][j] = 0.f;
    __syncthreads();

    // 4-deep prefetch queue
    float xq[4];
    #pragma unroll
    for (int k = 0; k < 4; k++)
        xq[k] = g_xw[(size_t)(k*BB + b)*HH + j];

    #pragma unroll 4
    for (int s = 0; s < SS; s++) {
        float xcur = xq[s & 3];
        if (s + 4 < SS)
            xq[s & 3] = g_xw[(size_t)((s+4)*BB + b)*HH + j];

        const float* hp = hbuf[s & 1] + half*32;
        float a0 = 0.f, a1 = 0.f, a2 = 0.f, a3 = 0.f;
        #pragma unroll
        for (int k = 0; k < 32; k += 4) {
            float4 hv = *(const float4*)(hp + k);
            a0 += w[k+0]*hv.x; a1 += w[k+1]*hv.y;
            a2 += w[k+2]*hv.z; a3 += w[k+3]*hv.w;
        }
        float ps = (a0 + a1) + (a2 + a3);
        ps += __shfl_xor_sync(0xffffffffu, ps, 1);
        float hnew = fast_tanh(xcur + ps);
        if (half == 0) {
            hbuf[(s + 1) & 1][j] = hnew;
            g_hs[(size_t)(s*BB + b)*HH + j] = hnew;
        }
        __syncthreads();
    }
}

// ---------------- tf32 tensor-core GEMM (cp.async): C = A @ W^T + bias ------
// MODE 0: +bias  MODE 1: +bias,relu
// MODE 2: C = LN(R1 + acc+bias)
// MODE 3: atomic-accumulate LN(LN(R1+acc+bias)+R2) into g_pool (no C write)
// MODE 4: split output: block col 0 -> g_proj fp32; cols 1..3 -> g_qkvh bf16
#define LDT 36
#define A_STAGE (128*LDT)
#define B_STAGE (128*LDT)
#define CS_LD 132

template<int MODE>
__global__ __launch_bounds__(256, 2) void mma_gemm(
    const float* __restrict__ A, const float* __restrict__ W,
    const float* __restrict__ bias,
    const float* __restrict__ R1, const float* __restrict__ R2,
    const float* __restrict__ gA, const float* __restrict__ bA,
    const float* __restrict__ gB, const float* __restrict__ bB,
    float* __restrict__ C, int M, int N, int K, int rs1, int rs2)
{
    extern __shared__ float sh[];
    float* As = sh;
    float* Bs = sh + 2*A_STAGE;
    float* Cs = sh;

    const int tid = threadIdx.x;
    const int lane = tid & 31, wid = tid >> 5;
    const int wm = wid >> 2, wn = wid & 3;
    const int g = lane >> 2, t4 = lane & 3;
    const int bm = blockIdx.y * 128;
    const int bn = blockIdx.x * 128;
    const int lrow = tid >> 3;
    const int lcol = (tid & 7) << 2;

    float acc[4][4][4];
    #pragma unroll
    for (int mt = 0; mt < 4; mt++)
        #pragma unroll
        for (int nt = 0; nt < 4; nt++)
            #pragma unroll
            for (int i = 0; i < 4; i++) acc[mt][nt][i] = 0.f;

    const int nk = K >> 5;

    #define ISSUE_TILE(kt0, buf) do {                                           \
        float* Ab = As + (buf)*A_STAGE;                                         \
        float* Bb = Bs + (buf)*B_STAGE;                                         \
        _Pragma("unroll")                                                       \
        for (int i = 0; i < 4; i++) {                                           \
            int row = lrow + 32*i;                                              \
            unsigned d = (unsigned)__cvta_generic_to_shared(Ab + row*LDT + lcol); \
            CP_ASYNC16(d, &A[(size_t)(bm + row)*K + (kt0) + lcol]);             \
        }                                                                       \
        _Pragma("unroll")                                                       \
        for (int i = 0; i < 4; i++) {                                           \
            int row = lrow + 32*i;                                              \
            unsigned d = (unsigned)__cvta_generic_to_shared(Bb + row*LDT + lcol); \
            CP_ASYNC16(d, &W[(size_t)(bn + row)*K + (kt0) + lcol]);             \
        }                                                                       \
        CP_COMMIT();                                                            \
    } while (0)

    ISSUE_TILE(0, 0);

    for (int kt = 0; kt < nk; kt++) {
        int cur = kt & 1;
        if (kt + 1 < nk) { ISSUE_TILE((kt + 1) << 5, cur ^ 1); CP_WAIT1(); }
        else             { CP_WAIT0(); }
        __syncthreads();
        const float* Ab = As + cur*A_STAGE;
        const float* Bb = Bs + cur*B_STAGE;
        #pragma unroll
        for (int ks = 0; ks < 4; ks++) {
            int kb = ks*8;
            unsigned af[4][4];
            #pragma unroll
            for (int mt = 0; mt < 4; mt++) {
                int r0 = wm*64 + mt*16 + g;
                af[mt][0] = f2tf(Ab[r0*LDT + kb + t4]);
                af[mt][1] = f2tf(Ab[(r0+8)*LDT + kb + t4]);
                af[mt][2] = f2tf(Ab[r0*LDT + kb + t4 + 4]);
                af[mt][3] = f2tf(Ab[(r0+8)*LDT + kb + t4 + 4]);
            }
            #pragma unroll
            for (int nt = 0; nt < 4; nt++) {
                int nrow = wn*32 + nt*8 + g;
                unsigned bf[2];
                bf[0] = f2tf(Bb[nrow*LDT + kb + t4]);
                bf[1] = f2tf(Bb[nrow*LDT + kb + t4 + 4]);
                #pragma unroll
                for (int mt = 0; mt < 4; mt++) mma_tf32(acc[mt][nt], af[mt], bf);
            }
        }
        __syncthreads();
    }

    if (MODE <= 1) {
        #pragma unroll
        for (int mt = 0; mt < 4; mt++) {
            int row0 = bm + wm*64 + mt*16 + g;
            #pragma unroll
            for (int nt = 0; nt < 4; nt++) {
                int col = bn + wn*32 + nt*8 + t4*2;
                float2 bz = *(const float2*)&bias[col];
                float2 o0 = {acc[mt][nt][0] + bz.x, acc[mt][nt][1] + bz.y};
                float2 o1 = {acc[mt][nt][2] + bz.x, acc[mt][nt][3] + bz.y};
                if (MODE == 1) {
                    o0.x = fmaxf(o0.x, 0.f); o0.y = fmaxf(o0.y, 0.f);
                    o1.x = fmaxf(o1.x, 0.f); o1.y = fmaxf(o1.y, 0.f);
                }
                *(float2*)&C[(size_t)row0*N + col] = o0;
                *(float2*)&C[(size_t)(row0+8)*N + col] = o1;
            }
        }
    } else if (MODE == 4) {
        #pragma unroll
        for (int mt = 0; mt < 4; mt++) {
            int row0 = bm + wm*64 + mt*16 + g;
            #pragma unroll
            for (int nt = 0; nt < 4; nt++) {
                int coln = bn + wn*32 + nt*8 + t4*2;
                float2 bz = *(const float2*)&bias[coln];
                float2 o0 = {acc[mt][nt][0] + bz.x, acc[mt][nt][1] + bz.y};
                float2 o1 = {acc[mt][nt][2] + bz.x, acc[mt][nt][3] + bz.y};
                if (blockIdx.x == 0) {
                    int col = coln;
                    *(float2*)&g_proj[(size_t)row0*DD + col] = o0;
                    *(float2*)&g_proj[(size_t)(row0+8)*DD + col] = o1;
                } else {
                    int col = coln - DD;
                    *(unsigned*)&g_qkvh[(size_t)row0*QKVW + col] = pack_bf16(o0.x, o0.y);
                    *(unsigned*)&g_qkvh[(size_t)(row0+8)*QKVW + col] = pack_bf16(o1.x, o1.y);
                }
            }
        }
    } else {
        #pragma unroll
        for (int mt = 0; mt < 4; mt++) {
            int r0 = wm*64 + mt*16 + g;
            #pragma unroll
            for (int nt = 0; nt < 4; nt++) {
                int col = wn*32 + nt*8 + t4*2;
                *(float2*)&Cs[r0*CS_LD + col]     = make_float2(acc[mt][nt][0], acc[mt][nt][1]);
                *(float2*)&Cs[(r0+8)*CS_LD + col] = make_float2(acc[mt][nt][2], acc[mt][nt][3]);
            }
        }
        __syncthreads();
        float4 bz = *(const float4*)&bias[lane*4];
        float4 ga4 = *(const float4*)&gA[lane*4];
        float4 ba4 = *(const float4*)&bA[lane*4];
        #pragma unroll
        for (int i = 0; i < 16; i++) {
            int r = wid*16 + i;
            size_t gr = (size_t)(bm + r);
            float4 v = *(const float4*)&Cs[r*CS_LD + lane*4];
            float4 r1 = *(const float4*)&R1[gr*rs1 + lane*4];
            float v0 = v.x + bz.x + r1.x, v1 = v.y + bz.y + r1.y;
            float v2 = v.z + bz.z + r1.z, v3 = v.w + bz.w + r1.w;
            float s = v0 + v1 + v2 + v3;
            #pragma unroll
            for (int o = 16; o > 0; o >>= 1) s += __shfl_xor_sync(0xffffffffu, s, o);
            float mu = s * (1.f/128.f);
            float d0 = v0-mu, d1 = v1-mu, d2 = v2-mu, d3 = v3-mu;
            float qv = d0*d0 + d1*d1 + d2*d2 + d3*d3;
            #pragma unroll
            for (int o = 16; o > 0; o >>= 1) qv += __shfl_xor_sync(0xffffffffu, qv, o);
            float inv = rsqrtf(qv * (1.f/128.f) + 1e-5f);
            float x0 = d0*inv*ga4.x + ba4.x;
            float x1 = d1*inv*ga4.y + ba4.y;
            float x2 = d2*inv*ga4.z + ba4.z;
            float x3 = d3*inv*ga4.w + ba4.w;
            if (MODE == 2) {
                *(float4*)&C[gr*DD + lane*4] = make_float4(x0, x1, x2, x3);
            } else {
                float4 r2 = *(const float4*)&R2[gr*rs2 + lane*4];
                float4 gb4 = *(const float4*)&gB[lane*4];
                float4 bb4 = *(const float4*)&bB[lane*4];
                float u0 = x0 + r2.x, u1 = x1 + r2.y, u2 = x2 + r2.z, u3 = x3 + r2.w;
                float s2 = u0 + u1 + u2 + u3;
                #pragma unroll
                for (int o = 16; o > 0; o >>= 1) s2 += __shfl_xor_sync(0xffffffffu, s2, o);
                float mu2 = s2 * (1.f/128.f);
                float e0 = u0-mu2, e1 = u1-mu2, e2 = u2-mu2, e3 = u3-mu2;
                float q2 = e0*e0 + e1*e1 + e2*e2 + e3*e3;
                #pragma unroll
                for (int o = 16; o > 0; o >>= 1) q2 += __shfl_xor_sync(0xffffffffu, q2, o);
                float inv2 = rsqrtf(q2 * (1.f/128.f) + 1e-5f);
                int bb = (int)(gr & 63);
                float* pp = &g_pool[bb*DD + lane*4];
                atomicAdd(pp + 0, e0*inv2*gb4.x + bb4.x);
                atomicAdd(pp + 1, e1*inv2*gb4.y + bb4.y);
                atomicAdd(pp + 2, e2*inv2*gb4.z + bb4.z);
                atomicAdd(pp + 3, e3*inv2*gb4.w + bb4.w);
            }
        }
    }
    #undef ISSUE_TILE
}

// ---------------- flash attention: all-bf16 MMA, no-max softmax -------------
#define TK 32
#define KVH 24
#define NT_TILES (SS/TK)
__global__ __launch_bounds__(256) void attn_mma(
    const __nv_bfloat16* __restrict__ qkvh, float* __restrict__ ctx)
{
    __shared__ __align__(16) __nv_bfloat16 Kt[2][TK][KVH];
    __shared__ __align__(16) __nv_bfloat16 Vt[2][TK][KVH];
    const int bh = blockIdx.x;
    const int b = bh >> 3, h = bh & 7;
    const int tid = threadIdx.x, lane = tid & 31, w = tid >> 5;
    const int g = lane >> 2, t4 = lane & 3;

    #define ISSUE_KV(tk_, buf) do {                                               \
        if (tid < 128) {                                                          \
            int row = (tid & 63) >> 1, ch = tid & 1;                              \
            int off = (tid < 64) ? DD : 2*DD;                                     \
            const __nv_bfloat16* src = qkvh +                                     \
                (size_t)(((tk_)*TK + row)*BB + b)*QKVW + off + h*HDD + ch*8;      \
            __nv_bfloat16* dst = (tid < 64) ? &Kt[buf][row][ch*8]                 \
                                            : &Vt[buf][row][ch*8];                \
            unsigned d = (unsigned)__cvta_generic_to_shared(dst);                 \
            CP_ASYNC16(d, src);                                                   \
        }                                                                         \
        CP_COMMIT();                                                              \
    } while (0)

    unsigned qa[4][4];
    #pragma unroll
    for (int mt = 0; mt < 4; mt++) {
        int r0 = w*64 + mt*16 + g;
        const __nv_bfloat16* p0 = qkvh + (size_t)(r0*BB + b)*QKVW + h*HDD;
        const __nv_bfloat16* p1 = p0 + (size_t)8*BB*QKVW;
        qa[mt][0] = *(const unsigned*)(p0 + 2*t4);
        qa[mt][1] = *(const unsigned*)(p1 + 2*t4);
        qa[mt][2] = *(const unsigned*)(p0 + 2*t4 + 8);
        qa[mt][3] = *(const unsigned*)(p1 + 2*t4 + 8);
    }

    float lsum[8], o[4][2][4];
    #pragma unroll
    for (int i = 0; i < 8; i++) lsum[i] = 0.f;
    #pragma unroll
    for (int mt = 0; mt < 4; mt++)
        #pragma unroll
        for (int n8 = 0; n8 < 2; n8++)
            #pragma unroll
            for (int i = 0; i < 4; i++) o[mt][n8][i] = 0.f;

    ISSUE_KV(0, 0);

    for (int tk = 0; tk < NT_TILES; tk++) {
        int cur = tk & 1;
        if (tk + 1 < NT_TILES) { ISSUE_KV(tk + 1, cur ^ 1); CP_WAIT1(); }
        else                   { CP_WAIT0(); }
        __syncthreads();

        float sc[4][4][4];
        #pragma unroll
        for (int mt = 0; mt < 4; mt++)
            #pragma unroll
            for (int nt = 0; nt < 4; nt++)
                #pragma unroll
                for (int i = 0; i < 4; i++) sc[mt][nt][i] = 0.f;
        #pragma unroll
        for (int nt = 0; nt < 4; nt++) {
            unsigned bf[2];
            bf[0] = *(const unsigned*)&Kt[cur][nt*8+g][2*t4];
            bf[1] = *(const unsigned*)&Kt[cur][nt*8+g][2*t4 + 8];
            #pragma unroll
            for (int mt = 0; mt < 4; mt++) mma_bf16(sc[mt][nt], qa[mt], bf);
        }

        #pragma unroll
        for (int mt = 0; mt < 4; mt++) {
            #pragma unroll
            for (int nt = 0; nt < 4; nt++) {
                float e0 = ex2(sc[mt][nt][0]);
                float e1 = ex2(sc[mt][nt][1]);
                float e2 = ex2(sc[mt][nt][2]);
                float e3 = ex2(sc[mt][nt][3]);
                sc[mt][nt][0] = e0; sc[mt][nt][1] = e1;
                sc[mt][nt][2] = e2; sc[mt][nt][3] = e3;
                lsum[mt*2+0] += e0 + e1;
                lsum[mt*2+1] += e2 + e3;
            }
        }

        #pragma unroll
        for (int u = 0; u < 2; u++) {
            unsigned vb[2][2];
            #pragma unroll
            for (int n8 = 0; n8 < 2; n8++) {
                int d = n8*8 + g;
                unsigned lo0 = *(const unsigned short*)&Vt[cur][u*16 + 2*t4][d];
                unsigned hi0 = *(const unsigned short*)&Vt[cur][u*16 + 2*t4 + 1][d];
                unsigned lo1 = *(const unsigned short*)&Vt[cur][u*16 + 2*t4 + 8][d];
                unsigned hi1 = *(const unsigned short*)&Vt[cur][u*16 + 2*t4 + 9][d];
                vb[n8][0] = lo0 | (hi0 << 16);
                vb[n8][1] = lo1 | (hi1 << 16);
            }
            #pragma unroll
            for (int mt = 0; mt < 4; mt++) {
                unsigned pa[4];
                pa[0] = pack_bf16(sc[mt][u*2][0],   sc[mt][u*2][1]);
                pa[1] = pack_bf16(sc[mt][u*2][2],   sc[mt][u*2][3]);
                pa[2] = pack_bf16(sc[mt][u*2+1][0], sc[mt][u*2+1][1]);
                pa[3] = pack_bf16(sc[mt][u*2+1][2], sc[mt][u*2+1][3]);
                mma_bf16(o[mt][0], pa, vb[0]);
                mma_bf16(o[mt][1], pa, vb[1]);
            }
        }
        __syncthreads();
    }

    float inv[8];
    #pragma unroll
    for (int i = 0; i < 8; i++) {
        float l = lsum[i];
        l += __shfl_xor_sync(0xffffffffu, l, 1);
        l += __shfl_xor_sync(0xffffffffu, l, 2);
        inv[i] = 1.f / l;
    }
    #pragma unroll
    for (int mt = 0; mt < 4; mt++) {
        int r0 = w*64 + mt*16 + g;
        #pragma unroll
        for (int n8 = 0; n8 < 2; n8++) {
            int col = h*HDD + n8*8 + 2*t4;
            float2 lo = { o[mt][n8][0]*inv[mt*2],   o[mt][n8][1]*inv[mt*2]   };
            float2 hi = { o[mt][n8][2]*inv[mt*2+1], o[mt][n8][3]*inv[mt*2+1] };
            *(float2*)&ctx[(size_t)(r0*BB + b)*DD + col]     = lo;
            *(float2*)&ctx[(size_t)((r0+8)*BB + b)*DD + col] = hi;
        }
    }
    #undef ISSUE_KV
}

// ---------------- head: tanh(pool/S @ Wf^T + bf) ----------------------------
__global__ __launch_bounds__(128) void final_kernel(
    const float* __restrict__ Wf, const float* __restrict__ bf,
    float* __restrict__ out)
{
    int b = blockIdx.x, tid = threadIdx.x;
    __shared__ float p[DD];
    p[tid] = g_pool[b*DD + tid] * (1.f/(float)SS);
    __syncthreads();
    int i = tid >> 2, q = tid & 3;
    const float* w = Wf + (size_t)i*DD + q*32;
    const float* pv = p + q*32;
    float acc = 0.f;
    #pragma unroll
    for (int k = 0; k < 32; k += 4) {
        float4 wv = *(const float4*)(w + k);
        float4 xv = *(const float4*)(pv + k);
        acc += wv.x*xv.x + wv.y*xv.y + wv.z*xv.z + wv.w*xv.w;
    }
    acc += __shfl_xor_sync(0xffffffffu, acc, 1);
    acc += __shfl_xor_sync(0xffffffffu, acc, 2);
    if (q == 0) out[b*II + i] = tanhf(acc + bf[i]);
}

// ---------------- launch ----------------------------------------------------
static const int GEMM_SMEM = (2*A_STAGE + 2*B_STAGE) * (int)sizeof(float); // 73728

extern "C" void kernel_launch(void* const* d_in, const int* in_sizes, int n_in,
                              void* d_out, int out_size)
{
    const float* x    = (const float*)d_in[0];
    const float* W_ih = (const float*)d_in[1];
    const float* b_ih = (const float*)d_in[2];
    const float* W_hh = (const float*)d_in[3];
    const float* b_hh = (const float*)d_in[4];
    const float* Wp   = (const float*)d_in[5];
    const float* bp   = (const float*)d_in[6];
    const float* Wqkv = (const float*)d_in[7];
    const float* bqkv = (const float*)d_in[8];
    const float* Wo   = (const float*)d_in[9];
    const float* bo   = (const float*)d_in[10];
    const float* g1   = (const float*)d_in[11];
    const float* be1  = (const float*)d_in[12];
    const float* W1   = (const float*)d_in[13];
    const float* b1   = (const float*)d_in[14];
    const float* W2   = (const float*)d_in[15];
    const float* b2   = (const float*)d_in[16];
    const float* g2   = (const float*)d_in[17];
    const float* be2  = (const float*)d_in[18];
    const float* gn   = (const float*)d_in[19];
    const float* bn   = (const float*)d_in[20];
    const float* Wf   = (const float*)d_in[21];
    const float* bf   = (const float*)d_in[22];
    float* out = (float*)d_out;

    float *p_hs, *p_proj, *p_ctx, *p_x1, *p_ffh, *p_Wcat, *p_bcat;
    __nv_bfloat16* p_qkvh;
    cudaGetSymbolAddress((void**)&p_hs,    g_hs);
    cudaGetSymbolAddress((void**)&p_proj,  g_proj);
    cudaGetSymbolAddress((void**)&p_qkvh,  g_qkvh);
    cudaGetSymbolAddress((void**)&p_ctx,   g_ctx);
    cudaGetSymbolAddress((void**)&p_x1,    g_x1);
    cudaGetSymbolAddress((void**)&p_ffh,   g_ffh);
    cudaGetSymbolAddress((void**)&p_Wcat,  g_Wcat);
    cudaGetSymbolAddress((void**)&p_bcat,  g_bcat);

    cudaFuncSetAttribute(mma_gemm<1>, cudaFuncAttributeMaxDynamicSharedMemorySize, GEMM_SMEM);
    cudaFuncSetAttribute(mma_gemm<2>, cudaFuncAttributeMaxDynamicSharedMemorySize, GEMM_SMEM);
    cudaFuncSetAttribute(mma_gemm<3>, cudaFuncAttributeMaxDynamicSharedMemorySize, GEMM_SMEM);
    cudaFuncSetAttribute(mma_gemm<4>, cudaFuncAttributeMaxDynamicSharedMemorySize, GEMM_SMEM);

    // 0. build weights + zero pool accumulator
    fold_kernel<<<NCAT, 64>>>(Wqkv, bqkv, Wp, bp);
    zero_pool_kernel<<<BB, 128>>>();
    // 1. parallel part of the RNN cell
    xw_kernel<<<SS*BB, 64>>>(x, W_ih, b_ih, b_hh);
    // 2. sequential recurrence (4-deep prefetch)
    rnn_kernel<<<BB, 128>>>(W_hh);
    // 3. split-output GEMM: proj fp32 + qkv bf16 (q pre-scaled)
    mma_gemm<4><<<dim3(NCAT/128, MR/128), 256, GEMM_SMEM>>>(
        p_hs, p_Wcat, p_bcat, nullptr, nullptr, nullptr, nullptr, nullptr, nullptr,
        nullptr, MR, NCAT, HH, 0, 0);
    // 4. attention (all-bf16 MMA, no-max softmax)
    attn_mma<<<BB*NHH, 256>>>(p_qkvh, p_ctx);
    // 5. x1 = LN(proj + ctx@Wo^T + bo)
    mma_gemm<2><<<dim3(1, MR/128), 256, GEMM_SMEM>>>(
        p_ctx, Wo, bo, p_proj, nullptr, g1, be1, nullptr, nullptr,
        p_x1, MR, DD, DD, DD, 0);
    // 6. ffh = relu(x1 @ W1^T + b1)
    mma_gemm<1><<<dim3(2, MR/128), 256, GEMM_SMEM>>>(
        p_x1, W1, b1, nullptr, nullptr, nullptr, nullptr, nullptr, nullptr,
        p_ffh, MR, FF, DD, 0, 0);
    // 7. LN(LN(x1 + ffh@W2^T + b2) + proj) -> atomic pool accumulate
    mma_gemm<3><<<dim3(1, MR/128), 256, GEMM_SMEM>>>(
        p_ffh, W2, b2, p_x1, p_proj, g2, be2, gn, bn,
        nullptr, MR, DD, FF, DD, DD);
    // 8. pooled head
    final_kernel<<<BB, 128>>>(Wf, bf, out);
}